// round 11
// baseline (speedup 1.0000x reference)
#include <cuda_runtime.h>
#include <cuda_bf16.h>
#include <cstdint>

#define B_  8
#define S_  4096
#define D_  256
#define DV_ 256
#define EPS_ 1e-6f

#define SPLITS 4
#define S_PER  (S_ / SPLITS)     // 1024
#define KC     32                // k-chunk (bf16 elems)
#define NT     128               // threads per CTA (4 warps)

// ---------------- kv_kernel smem: [k][col] tiles, 64-wide ------------------
#define LDA_KV 144               // 64 bf16 = 128B + 16 pad (4 words mod 32)
#define LDB_KV 144
#define A_TILE_KV (KC * LDA_KV)  // 4608
#define B_TILE_KV (KC * LDB_KV)  // 4608
#define OFFK_AHI 0
#define OFFK_ALO A_TILE_KV
#define OFFK_BHI (2 * A_TILE_KV)
#define OFFK_BLO (3 * A_TILE_KV)
#define BUF_KV   (4 * A_TILE_KV)                  // 18432
#define SMEM_KV  (2 * BUF_KV)                     // 36864

// ---------------- out_kernel smem: [row][k] tiles, 64 rows ------------------
#define LDSB   80
#define TILE64 (64 * LDSB)       // 5120
#define OFF_AHI 0
#define OFF_ALO TILE64
#define OFF_BHI (2 * TILE64)
#define OFF_BLO (3 * TILE64)
#define BUF_OUT (4 * TILE64)                      // 20480
#define SMEM_OUT (2 * BUF_OUT)                    // 40960

__device__ float g_part[SPLITS * B_ * DV_ * D_];   // 8 MB split-S partials
__device__ __nv_bfloat16 g_KVThi[B_ * DV_ * D_];   // KV^T hi [b][v][d]
__device__ __nv_bfloat16 g_KVTlo[B_ * DV_ * D_];   // KV^T lo [b][v][d]

// ---------------------------------------------------------------------------
__device__ __forceinline__ uint32_t smem_to_u32(const void* p) {
    uint32_t a;
    asm("{ .reg .u64 t; cvta.to.shared.u64 t, %1; cvt.u32.u64 %0, t; }"
        : "=r"(a) : "l"(p));
    return a;
}
__device__ __forceinline__ void ldmx4(uint32_t* r, uint32_t addr) {
    asm volatile("ldmatrix.sync.aligned.m8n8.x4.shared.b16 {%0,%1,%2,%3}, [%4];"
        : "=r"(r[0]), "=r"(r[1]), "=r"(r[2]), "=r"(r[3]) : "r"(addr));
}
__device__ __forceinline__ void ldmx4t(uint32_t* r, uint32_t addr) {
    asm volatile("ldmatrix.sync.aligned.m8n8.x4.trans.shared.b16 {%0,%1,%2,%3}, [%4];"
        : "=r"(r[0]), "=r"(r[1]), "=r"(r[2]), "=r"(r[3]) : "r"(addr));
}
__device__ __forceinline__ void mma16816(float* c, const uint32_t* a, const uint32_t* b) {
    asm volatile(
        "mma.sync.aligned.m16n8k16.row.col.f32.bf16.bf16.f32 "
        "{%0,%1,%2,%3}, {%4,%5,%6,%7}, {%8,%9}, {%0,%1,%2,%3};"
        : "+f"(c[0]), "+f"(c[1]), "+f"(c[2]), "+f"(c[3])
        : "r"(a[0]), "r"(a[1]), "r"(a[2]), "r"(a[3]), "r"(b[0]), "r"(b[1]));
}
__device__ __forceinline__ void cp_async16(uint32_t dst, const void* src) {
    asm volatile("cp.async.cg.shared.global [%0], [%1], 16;"
        :: "r"(dst), "l"(src) : "memory");
}
#define CP_COMMIT() asm volatile("cp.async.commit_group;" ::: "memory")
#define CP_WAIT0()  asm volatile("cp.async.wait_group 0;" ::: "memory")

// Truncation split: hi = top-16-bits (exact bf16), lo = rn_bf16(x - hi).
__device__ __forceinline__ void split2f(float x0, float x1, uint32_t& h, uint32_t& l) {
    uint32_t u0 = __float_as_uint(x0), u1 = __float_as_uint(x1);
    asm("prmt.b32 %0, %1, %2, 0x7632;" : "=r"(h) : "r"(u0), "r"(u1));
    float r0 = x0 - __uint_as_float(u0 & 0xFFFF0000u);
    float r1 = x1 - __uint_as_float(u1 & 0xFFFF0000u);
    asm("cvt.rn.bf16x2.f32 %0, %1, %2;" : "=r"(l) : "f"(r1), "f"(r0));
}

// ---------------------------------------------------------------------------
// kv MMA chunk: tiles [k][col] (64-wide), ldmatrix.trans. Warp tile 32x32.
// ---------------------------------------------------------------------------
__device__ __forceinline__ void warp_chunk_mma_kv(
    uint32_t buf, int lane, int wm, int wn, float (*acc)[4])
{
    const uint32_t aHi = buf + OFFK_AHI, aLo = buf + OFFK_ALO;
    const uint32_t bHi = buf + OFFK_BHI, bLo = buf + OFFK_BLO;
#pragma unroll
    for (int ks = 0; ks < 2; ks++) {
        int krA = ks * 16 + (lane & 7) + ((lane >> 4) & 1) * 8;
        int mcA = wm + ((lane >> 3) & 1) * 8;
        uint32_t aoff = (uint32_t)(krA * LDA_KV + mcA * 2);
        uint32_t ah[2][4], al[2][4];
#pragma unroll
        for (int mi = 0; mi < 2; mi++) {
            ldmx4t(ah[mi], aHi + aoff + mi * 32);
            ldmx4t(al[mi], aLo + aoff + mi * 32);
        }
        int krB = ks * 16 + (lane & 7) + ((lane >> 3) & 1) * 8;
        int ncB = wn + (lane >> 4) * 8;
        uint32_t boff = (uint32_t)(krB * LDB_KV + ncB * 2);
        uint32_t bh[4][2], bl[4][2];
#pragma unroll
        for (int pi = 0; pi < 2; pi++) {
            uint32_t r4[4];
            ldmx4t(r4, bHi + boff + pi * 32);
            bh[2*pi][0] = r4[0]; bh[2*pi][1] = r4[1];
            bh[2*pi+1][0] = r4[2]; bh[2*pi+1][1] = r4[3];
            ldmx4t(r4, bLo + boff + pi * 32);
            bl[2*pi][0] = r4[0]; bl[2*pi][1] = r4[1];
            bl[2*pi+1][0] = r4[2]; bl[2*pi+1][1] = r4[3];
        }
#pragma unroll
        for (int mi = 0; mi < 2; mi++)
#pragma unroll
            for (int ni = 0; ni < 4; ni++)
                mma16816(acc[mi * 4 + ni], ah[mi], bh[ni]);
#pragma unroll
        for (int mi = 0; mi < 2; mi++)
#pragma unroll
            for (int ni = 0; ni < 4; ni++)
                mma16816(acc[mi * 4 + ni], ah[mi], bl[ni]);
#pragma unroll
        for (int mi = 0; mi < 2; mi++)
#pragma unroll
            for (int ni = 0; ni < 4; ni++)
                mma16816(acc[mi * 4 + ni], al[mi], bh[ni]);
    }
}

// out MMA chunk: tiles [row][k], stride LDSB.
__device__ __forceinline__ void warp_chunk_mma_out(
    uint32_t buf, int lane, int wm, int wn, float (*acc)[4])
{
    const uint32_t aHi = buf + OFF_AHI, aLo = buf + OFF_ALO;
    const uint32_t bHi = buf + OFF_BHI, bLo = buf + OFF_BLO;
#pragma unroll
    for (int ks = 0; ks < 2; ks++) {
        uint32_t aoff = (uint32_t)((wm + (lane & 15)) * LDSB
                                   + ((lane >> 4) * 8 + ks * 16) * 2);
        uint32_t ah[2][4], al[2][4];
#pragma unroll
        for (int mi = 0; mi < 2; mi++) {
            ldmx4(ah[mi], aHi + aoff + mi * 16 * LDSB);
            ldmx4(al[mi], aLo + aoff + mi * 16 * LDSB);
        }
        uint32_t boff = (uint32_t)((wn + (lane & 7) + ((lane >> 4) << 3)) * LDSB
                                   + (((lane >> 3) & 1) * 8 + ks * 16) * 2);
        uint32_t bh[4][2], bl[4][2];
#pragma unroll
        for (int pi = 0; pi < 2; pi++) {
            uint32_t r4[4];
            ldmx4(r4, bHi + boff + pi * 16 * LDSB);
            bh[2*pi][0] = r4[0]; bh[2*pi][1] = r4[1];
            bh[2*pi+1][0] = r4[2]; bh[2*pi+1][1] = r4[3];
            ldmx4(r4, bLo + boff + pi * 16 * LDSB);
            bl[2*pi][0] = r4[0]; bl[2*pi][1] = r4[1];
            bl[2*pi+1][0] = r4[2]; bl[2*pi+1][1] = r4[3];
        }
#pragma unroll
        for (int mi = 0; mi < 2; mi++)
#pragma unroll
            for (int ni = 0; ni < 4; ni++)
                mma16816(acc[mi * 4 + ni], ah[mi], bh[ni]);
#pragma unroll
        for (int mi = 0; mi < 2; mi++)
#pragma unroll
            for (int ni = 0; ni < 4; ni++)
                mma16816(acc[mi * 4 + ni], ah[mi], bl[ni]);
#pragma unroll
        for (int mi = 0; mi < 2; mi++)
#pragma unroll
            for (int ni = 0; ni < 4; ni++)
                mma16816(acc[mi * 4 + ni], al[mi], bh[ni]);
    }
}

// ---------------------------------------------------------------------------
// Kernel 1: partial KV^T[v,d] = sum_{s in split} V[s,v] * (relu(K[s,d])+eps)
// 128-thread CTAs, tile 64(v) x 64(d), target 5 CTAs/SM.
// Grid (16, SPLITS, B) = 512 CTAs -> single resident wave.
// ---------------------------------------------------------------------------
__global__ __launch_bounds__(NT, 5)
void kv_kernel(const float* __restrict__ K, const float* __restrict__ V) {
    extern __shared__ __align__(16) char smem[];
    const uint32_t sb = smem_to_u32(smem);

    const int t = threadIdx.x, lane = t & 31, wid = t >> 5;
    const int wm = (wid & 1) * 32, wn = (wid >> 1) * 32;
    const int b = blockIdx.z, p = blockIdx.y;
    const int v0 = (blockIdx.x & 3) * 64, d0 = (blockIdx.x >> 2) * 64;

    const float* __restrict__ Vb = V + (size_t)b * S_ * DV_;
    const float* __restrict__ Kb = K + (size_t)b * S_ * D_;

    float acc[8][4];
#pragma unroll
    for (int i = 0; i < 8; i++)
#pragma unroll
        for (int j = 0; j < 4; j++) acc[i][j] = 0.0f;

    // slots: idx = t + i*128 (i<4): s = idx>>4 (0..31), c4 = (idx&15)*4
    float4 ra[4], rb[4];
    {
        const int s_c = p * S_PER;
#pragma unroll
        for (int i = 0; i < 4; i++) {
            int idx = t + i * NT;
            int s = idx >> 4, c4 = (idx & 15) * 4;
            ra[i] = *(const float4*)(Vb + (size_t)(s_c + s) * DV_ + v0 + c4);
            rb[i] = *(const float4*)(Kb + (size_t)(s_c + s) * D_ + d0 + c4);
        }
    }

    const int NC = S_PER / KC;   // 32
    for (int c = 0; c < NC; c++) {
        char* base = smem + (size_t)(c & 1) * BUF_KV;
#pragma unroll
        for (int i = 0; i < 4; i++) {
            int idx = t + i * NT;
            int s = idx >> 4, c8 = (idx & 15) * 8;
            uint32_t h01, l01, h23, l23;
            split2f(ra[i].x, ra[i].y, h01, l01);
            split2f(ra[i].z, ra[i].w, h23, l23);
            *(uint2*)(base + OFFK_AHI + s * LDA_KV + c8) = make_uint2(h01, h23);
            *(uint2*)(base + OFFK_ALO + s * LDA_KV + c8) = make_uint2(l01, l23);
            float b0 = fmaxf(rb[i].x, 0.f) + EPS_;
            float b1 = fmaxf(rb[i].y, 0.f) + EPS_;
            float b2 = fmaxf(rb[i].z, 0.f) + EPS_;
            float b3 = fmaxf(rb[i].w, 0.f) + EPS_;
            split2f(b0, b1, h01, l01);
            split2f(b2, b3, h23, l23);
            *(uint2*)(base + OFFK_BHI + s * LDB_KV + c8) = make_uint2(h01, h23);
            *(uint2*)(base + OFFK_BLO + s * LDB_KV + c8) = make_uint2(l01, l23);
        }
        __syncthreads();
        if (c + 1 < NC) {
            const int s_c = p * S_PER + (c + 1) * KC;
#pragma unroll
            for (int i = 0; i < 4; i++) {
                int idx = t + i * NT;
                int s = idx >> 4, c4 = (idx & 15) * 4;
                ra[i] = *(const float4*)(Vb + (size_t)(s_c + s) * DV_ + v0 + c4);
                rb[i] = *(const float4*)(Kb + (size_t)(s_c + s) * D_ + d0 + c4);
            }
        }
        warp_chunk_mma_kv(sb + (uint32_t)(c & 1) * BUF_KV, lane, wm, wn, acc);
    }

    // Epilogue: C[v,d] -> g_part
    float* dst = g_part + (size_t)(p * B_ + b) * DV_ * D_;
    const int rr = lane >> 2, cc = (lane & 3) * 2;
#pragma unroll
    for (int mi = 0; mi < 2; mi++)
#pragma unroll
        for (int ni = 0; ni < 4; ni++) {
            int row = v0 + wm + mi * 16 + rr;
            int col = d0 + wn + ni * 8 + cc;
            float* cp = acc[mi * 4 + ni];
            *(float2*)(dst + (size_t)row * D_ + col)       = make_float2(cp[0], cp[1]);
            *(float2*)(dst + (size_t)(row + 8) * D_ + col) = make_float2(cp[2], cp[3]);
        }
}

// ---------------------------------------------------------------------------
// Kernel 2: sum partials (fp32), split, write bf16 hi/lo KVT.
// ---------------------------------------------------------------------------
__global__ __launch_bounds__(256)
void reduce_kernel() {
    const int i = blockIdx.x * 256 + threadIdx.x;  // float4 group, 131072 total
    const size_t stride4 = (size_t)B_ * DV_ * D_ / 4;
    float4 acc = make_float4(0.f, 0.f, 0.f, 0.f);
#pragma unroll
    for (int p = 0; p < SPLITS; p++) {
        float4 v = ((const float4*)g_part)[p * stride4 + i];
        acc.x += v.x; acc.y += v.y; acc.z += v.z; acc.w += v.w;
    }
    uint32_t h01, l01, h23, l23;
    split2f(acc.x, acc.y, h01, l01);
    split2f(acc.z, acc.w, h23, l23);
    ((uint2*)g_KVThi)[i] = make_uint2(h01, h23);
    ((uint2*)g_KVTlo)[i] = make_uint2(l01, l23);
}

// ---------------------------------------------------------------------------
// Kernel 3: out[q,v] = (relu(Q)+eps)[q,d] @ KVT[v,d]^T
// 128-thread CTAs, tile 64(q) x 64(v). A from regs, B via cp.async.
// Grid (4, 64, B) = 2048 CTAs.
// ---------------------------------------------------------------------------
__global__ __launch_bounds__(NT, 4)
void out_kernel(const float* __restrict__ Q, float* __restrict__ O) {
    extern __shared__ __align__(16) char smem[];
    const uint32_t sb = smem_to_u32(smem);

    const int t = threadIdx.x, lane = t & 31, wid = t >> 5;
    const int wm = (wid & 1) * 32, wn = (wid >> 1) * 32;
    const int b = blockIdx.z;
    const int q0 = blockIdx.y * 64, v0 = blockIdx.x * 64;

    const float* __restrict__ Qb = Q + (size_t)b * S_ * D_;
    const __nv_bfloat16* __restrict__ Chi = g_KVThi + (size_t)b * DV_ * D_;
    const __nv_bfloat16* __restrict__ Clo = g_KVTlo + (size_t)b * DV_ * D_;

    float acc[8][4];
#pragma unroll
    for (int i = 0; i < 8; i++)
#pragma unroll
        for (int j = 0; j < 4; j++) acc[i][j] = 0.0f;

    // prologue: B(0) via cp.async, A(0) via LDG
    {
#pragma unroll
        for (int i = 0; i < 2; i++) {
            int idx = t + i * NT;
            int rowB = idx >> 2, sg = idx & 3;
            uint32_t doff = (uint32_t)(rowB * LDSB + sg * 16);
            cp_async16(sb + OFF_BHI + doff, Chi + (size_t)(v0 + rowB) * D_ + sg * 8);
            cp_async16(sb + OFF_BLO + doff, Clo + (size_t)(v0 + rowB) * D_ + sg * 8);
        }
        CP_COMMIT();
    }
    float4 rq[4];
#pragma unroll
    for (int i = 0; i < 4; i++) {
        int idx = t + i * NT;
        rq[i] = *(const float4*)(Qb + (size_t)(q0 + (idx >> 3)) * D_ + (idx & 7) * 4);
    }

    const int NC = D_ / KC;   // 8
    for (int c = 0; c < NC; c++) {
        char* base = smem + (size_t)(c & 1) * BUF_OUT;
#pragma unroll
        for (int i = 0; i < 4; i++) {
            int idx = t + i * NT;
            int row = idx >> 3, f4 = idx & 7;
            float a0 = fmaxf(rq[i].x, 0.f) + EPS_;
            float a1 = fmaxf(rq[i].y, 0.f) + EPS_;
            float a2 = fmaxf(rq[i].z, 0.f) + EPS_;
            float a3 = fmaxf(rq[i].w, 0.f) + EPS_;
            uint32_t h01, l01, h23, l23;
            split2f(a0, a1, h01, l01); split2f(a2, a3, h23, l23);
            *(uint2*)(base + OFF_AHI + row * LDSB + f4 * 8) = make_uint2(h01, h23);
            *(uint2*)(base + OFF_ALO + row * LDSB + f4 * 8) = make_uint2(l01, l23);
        }
        CP_WAIT0();          // B(c) landed (this thread's copies)
        __syncthreads();     // all copies + A staging visible
        if (c + 1 < NC) {
            const int dc = (c + 1) * KC;
            uint32_t nb = sb + (uint32_t)((~c & 1) * BUF_OUT);
#pragma unroll
            for (int i = 0; i < 2; i++) {
                int idx = t + i * NT;
                int rowB = idx >> 2, sg = idx & 3;
                uint32_t doff = (uint32_t)(rowB * LDSB + sg * 16);
                cp_async16(nb + OFF_BHI + doff, Chi + (size_t)(v0 + rowB) * D_ + dc + sg * 8);
                cp_async16(nb + OFF_BLO + doff, Clo + (size_t)(v0 + rowB) * D_ + dc + sg * 8);
            }
            CP_COMMIT();
#pragma unroll
            for (int i = 0; i < 4; i++) {
                int idx = t + i * NT;
                rq[i] = *(const float4*)(Qb + (size_t)(q0 + (idx >> 3)) * D_ + dc + (idx & 7) * 4);
            }
        }
        warp_chunk_mma_out(sb + (uint32_t)(c & 1) * BUF_OUT, lane, wm, wn, acc);
    }

    // Epilogue: C[q,v] -> O
    float* dst = O + (size_t)b * S_ * DV_;
    const int rr = lane >> 2, cc = (lane & 3) * 2;
#pragma unroll
    for (int mi = 0; mi < 2; mi++)
#pragma unroll
        for (int ni = 0; ni < 4; ni++) {
            int row = q0 + wm + mi * 16 + rr;
            int col = v0 + wn + ni * 8 + cc;
            float* cp = acc[mi * 4 + ni];
            *(float2*)(dst + (size_t)row * DV_ + col)       = make_float2(cp[0], cp[1]);
            *(float2*)(dst + (size_t)(row + 8) * DV_ + col) = make_float2(cp[2], cp[3]);
        }
}

extern "C" void kernel_launch(void* const* d_in, const int* in_sizes, int n_in,
                              void* d_out, int out_size) {
    const float* Q = (const float*)d_in[0];
    const float* K = (const float*)d_in[1];
    const float* V = (const float*)d_in[2];
    float* O = (float*)d_out;

    cudaFuncSetAttribute(kv_kernel,  cudaFuncAttributeMaxDynamicSharedMemorySize, SMEM_KV);
    cudaFuncSetAttribute(out_kernel, cudaFuncAttributeMaxDynamicSharedMemorySize, SMEM_OUT);

    kv_kernel<<<dim3(16, SPLITS, B_), NT, SMEM_KV>>>(K, V);
    reduce_kernel<<<512, 256>>>();
    out_kernel<<<dim3(4, 64, B_), NT, SMEM_OUT>>>(Q, O);
}

// round 12
// speedup vs baseline: 1.0165x; 1.0165x over previous
#include <cuda_runtime.h>
#include <cuda_bf16.h>
#include <cstdint>

#define B_  8
#define S_  4096
#define D_  256
#define DV_ 256
#define EPS_ 1e-6f

#define SPLITS 4
#define S_PER  (S_ / SPLITS)     // 1024
#define KC     32                // k-chunk (bf16 elems)
#define NT     128               // threads per CTA (4 warps)

// ---------------- kv_kernel smem: [k][col] tiles, 64-wide ------------------
#define LDA_KV 144               // 64 bf16 = 128B + 16 pad (4 words mod 32)
#define LDB_KV 144
#define A_TILE_KV (KC * LDA_KV)  // 4608
#define B_TILE_KV (KC * LDB_KV)  // 4608
#define OFFK_AHI 0
#define OFFK_ALO A_TILE_KV
#define OFFK_BHI (2 * A_TILE_KV)
#define OFFK_BLO (3 * A_TILE_KV)
#define BUF_KV   (4 * A_TILE_KV)                  // 18432
#define SMEM_KV  (2 * BUF_KV)                     // 36864

// ---------------- out_kernel smem: [row][k] tiles, 64 rows ------------------
#define LDSB   80
#define TILE64 (64 * LDSB)       // 5120
#define OFF_AHI 0
#define OFF_ALO TILE64
#define OFF_BHI (2 * TILE64)
#define OFF_BLO (3 * TILE64)
#define BUF_OUT (4 * TILE64)                      // 20480
#define SMEM_OUT (2 * BUF_OUT)                    // 40960

__device__ float g_part[SPLITS * B_ * DV_ * D_];   // 8 MB split-S partials
__device__ __nv_bfloat16 g_KVThi[B_ * DV_ * D_];   // KV^T hi [b][v][d]
__device__ __nv_bfloat16 g_KVTlo[B_ * DV_ * D_];   // KV^T lo [b][v][d]

// ---------------------------------------------------------------------------
__device__ __forceinline__ uint32_t smem_to_u32(const void* p) {
    uint32_t a;
    asm("{ .reg .u64 t; cvta.to.shared.u64 t, %1; cvt.u32.u64 %0, t; }"
        : "=r"(a) : "l"(p));
    return a;
}
__device__ __forceinline__ void ldmx4(uint32_t* r, uint32_t addr) {
    asm volatile("ldmatrix.sync.aligned.m8n8.x4.shared.b16 {%0,%1,%2,%3}, [%4];"
        : "=r"(r[0]), "=r"(r[1]), "=r"(r[2]), "=r"(r[3]) : "r"(addr));
}
__device__ __forceinline__ void ldmx4t(uint32_t* r, uint32_t addr) {
    asm volatile("ldmatrix.sync.aligned.m8n8.x4.trans.shared.b16 {%0,%1,%2,%3}, [%4];"
        : "=r"(r[0]), "=r"(r[1]), "=r"(r[2]), "=r"(r[3]) : "r"(addr));
}
__device__ __forceinline__ void mma16816(float* c, const uint32_t* a, const uint32_t* b) {
    asm volatile(
        "mma.sync.aligned.m16n8k16.row.col.f32.bf16.bf16.f32 "
        "{%0,%1,%2,%3}, {%4,%5,%6,%7}, {%8,%9}, {%0,%1,%2,%3};"
        : "+f"(c[0]), "+f"(c[1]), "+f"(c[2]), "+f"(c[3])
        : "r"(a[0]), "r"(a[1]), "r"(a[2]), "r"(a[3]), "r"(b[0]), "r"(b[1]));
}
__device__ __forceinline__ void cp_async16(uint32_t dst, const void* src) {
    asm volatile("cp.async.cg.shared.global [%0], [%1], 16;"
        :: "r"(dst), "l"(src) : "memory");
}
#define CP_COMMIT() asm volatile("cp.async.commit_group;" ::: "memory")
#define CP_WAIT0()  asm volatile("cp.async.wait_group 0;" ::: "memory")

// Truncation split: hi = top-16-bits (exact bf16), lo = rn_bf16(x - hi).
__device__ __forceinline__ void split2f(float x0, float x1, uint32_t& h, uint32_t& l) {
    uint32_t u0 = __float_as_uint(x0), u1 = __float_as_uint(x1);
    asm("prmt.b32 %0, %1, %2, 0x7632;" : "=r"(h) : "r"(u0), "r"(u1));
    float r0 = x0 - __uint_as_float(u0 & 0xFFFF0000u);
    float r1 = x1 - __uint_as_float(u1 & 0xFFFF0000u);
    asm("cvt.rn.bf16x2.f32 %0, %1, %2;" : "=r"(l) : "f"(r1), "f"(r0));
}

// ---------------------------------------------------------------------------
// kv MMA chunk: tiles [k][col] (64-wide), ldmatrix.trans. Warp tile 32x32.
// ---------------------------------------------------------------------------
__device__ __forceinline__ void warp_chunk_mma_kv(
    uint32_t buf, int lane, int wm, int wn, float (*acc)[4])
{
    const uint32_t aHi = buf + OFFK_AHI, aLo = buf + OFFK_ALO;
    const uint32_t bHi = buf + OFFK_BHI, bLo = buf + OFFK_BLO;
#pragma unroll
    for (int ks = 0; ks < 2; ks++) {
        int krA = ks * 16 + (lane & 7) + ((lane >> 4) & 1) * 8;
        int mcA = wm + ((lane >> 3) & 1) * 8;
        uint32_t aoff = (uint32_t)(krA * LDA_KV + mcA * 2);
        uint32_t ah[2][4], al[2][4];
#pragma unroll
        for (int mi = 0; mi < 2; mi++) {
            ldmx4t(ah[mi], aHi + aoff + mi * 32);
            ldmx4t(al[mi], aLo + aoff + mi * 32);
        }
        int krB = ks * 16 + (lane & 7) + ((lane >> 3) & 1) * 8;
        int ncB = wn + (lane >> 4) * 8;
        uint32_t boff = (uint32_t)(krB * LDB_KV + ncB * 2);
        uint32_t bh[4][2], bl[4][2];
#pragma unroll
        for (int pi = 0; pi < 2; pi++) {
            uint32_t r4[4];
            ldmx4t(r4, bHi + boff + pi * 32);
            bh[2*pi][0] = r4[0]; bh[2*pi][1] = r4[1];
            bh[2*pi+1][0] = r4[2]; bh[2*pi+1][1] = r4[3];
            ldmx4t(r4, bLo + boff + pi * 32);
            bl[2*pi][0] = r4[0]; bl[2*pi][1] = r4[1];
            bl[2*pi+1][0] = r4[2]; bl[2*pi+1][1] = r4[3];
        }
#pragma unroll
        for (int mi = 0; mi < 2; mi++)
#pragma unroll
            for (int ni = 0; ni < 4; ni++)
                mma16816(acc[mi * 4 + ni], ah[mi], bh[ni]);
#pragma unroll
        for (int mi = 0; mi < 2; mi++)
#pragma unroll
            for (int ni = 0; ni < 4; ni++)
                mma16816(acc[mi * 4 + ni], ah[mi], bl[ni]);
#pragma unroll
        for (int mi = 0; mi < 2; mi++)
#pragma unroll
            for (int ni = 0; ni < 4; ni++)
                mma16816(acc[mi * 4 + ni], al[mi], bh[ni]);
    }
}

// out MMA chunk: tiles [row][k], stride LDSB.
__device__ __forceinline__ void warp_chunk_mma_out(
    uint32_t buf, int lane, int wm, int wn, float (*acc)[4])
{
    const uint32_t aHi = buf + OFF_AHI, aLo = buf + OFF_ALO;
    const uint32_t bHi = buf + OFF_BHI, bLo = buf + OFF_BLO;
#pragma unroll
    for (int ks = 0; ks < 2; ks++) {
        uint32_t aoff = (uint32_t)((wm + (lane & 15)) * LDSB
                                   + ((lane >> 4) * 8 + ks * 16) * 2);
        uint32_t ah[2][4], al[2][4];
#pragma unroll
        for (int mi = 0; mi < 2; mi++) {
            ldmx4(ah[mi], aHi + aoff + mi * 16 * LDSB);
            ldmx4(al[mi], aLo + aoff + mi * 16 * LDSB);
        }
        uint32_t boff = (uint32_t)((wn + (lane & 7) + ((lane >> 4) << 3)) * LDSB
                                   + (((lane >> 3) & 1) * 8 + ks * 16) * 2);
        uint32_t bh[4][2], bl[4][2];
#pragma unroll
        for (int pi = 0; pi < 2; pi++) {
            uint32_t r4[4];
            ldmx4(r4, bHi + boff + pi * 16 * LDSB);
            bh[2*pi][0] = r4[0]; bh[2*pi][1] = r4[1];
            bh[2*pi+1][0] = r4[2]; bh[2*pi+1][1] = r4[3];
            ldmx4(r4, bLo + boff + pi * 16 * LDSB);
            bl[2*pi][0] = r4[0]; bl[2*pi][1] = r4[1];
            bl[2*pi+1][0] = r4[2]; bl[2*pi+1][1] = r4[3];
        }
#pragma unroll
        for (int mi = 0; mi < 2; mi++)
#pragma unroll
            for (int ni = 0; ni < 4; ni++)
                mma16816(acc[mi * 4 + ni], ah[mi], bh[ni]);
#pragma unroll
        for (int mi = 0; mi < 2; mi++)
#pragma unroll
            for (int ni = 0; ni < 4; ni++)
                mma16816(acc[mi * 4 + ni], ah[mi], bl[ni]);
#pragma unroll
        for (int mi = 0; mi < 2; mi++)
#pragma unroll
            for (int ni = 0; ni < 4; ni++)
                mma16816(acc[mi * 4 + ni], al[mi], bh[ni]);
    }
}

// ---------------------------------------------------------------------------
// Kernel 1: partial KV^T[v,d] = sum_{s in split} V[s,v] * (relu(K[s,d])+eps)
// 128-thread CTAs, tile 64(v) x 64(d), 4 CTAs/SM (regs ~120, NO squeeze).
// Grid (16, SPLITS, B) = 512 CTAs -> single balanced wave at occ 4.
// ---------------------------------------------------------------------------
__global__ __launch_bounds__(NT, 4)
void kv_kernel(const float* __restrict__ K, const float* __restrict__ V) {
    extern __shared__ __align__(16) char smem[];
    const uint32_t sb = smem_to_u32(smem);

    const int t = threadIdx.x, lane = t & 31, wid = t >> 5;
    const int wm = (wid & 1) * 32, wn = (wid >> 1) * 32;
    const int b = blockIdx.z, p = blockIdx.y;
    const int v0 = (blockIdx.x & 3) * 64, d0 = (blockIdx.x >> 2) * 64;

    const float* __restrict__ Vb = V + (size_t)b * S_ * DV_;
    const float* __restrict__ Kb = K + (size_t)b * S_ * D_;

    float acc[8][4];
#pragma unroll
    for (int i = 0; i < 8; i++)
#pragma unroll
        for (int j = 0; j < 4; j++) acc[i][j] = 0.0f;

    // slots: idx = t + i*128 (i<4): s = idx>>4 (0..31), c4 = (idx&15)*4
    float4 ra[4], rb[4];
    {
        const int s_c = p * S_PER;
#pragma unroll
        for (int i = 0; i < 4; i++) {
            int idx = t + i * NT;
            int s = idx >> 4, c4 = (idx & 15) * 4;
            ra[i] = *(const float4*)(Vb + (size_t)(s_c + s) * DV_ + v0 + c4);
            rb[i] = *(const float4*)(Kb + (size_t)(s_c + s) * D_ + d0 + c4);
        }
    }

    const int NC = S_PER / KC;   // 32
    for (int c = 0; c < NC; c++) {
        char* base = smem + (size_t)(c & 1) * BUF_KV;
#pragma unroll
        for (int i = 0; i < 4; i++) {
            int idx = t + i * NT;
            int s = idx >> 4, c8 = (idx & 15) * 8;
            uint32_t h01, l01, h23, l23;
            split2f(ra[i].x, ra[i].y, h01, l01);
            split2f(ra[i].z, ra[i].w, h23, l23);
            *(uint2*)(base + OFFK_AHI + s * LDA_KV + c8) = make_uint2(h01, h23);
            *(uint2*)(base + OFFK_ALO + s * LDA_KV + c8) = make_uint2(l01, l23);
            float b0 = fmaxf(rb[i].x, 0.f) + EPS_;
            float b1 = fmaxf(rb[i].y, 0.f) + EPS_;
            float b2 = fmaxf(rb[i].z, 0.f) + EPS_;
            float b3 = fmaxf(rb[i].w, 0.f) + EPS_;
            split2f(b0, b1, h01, l01);
            split2f(b2, b3, h23, l23);
            *(uint2*)(base + OFFK_BHI + s * LDB_KV + c8) = make_uint2(h01, h23);
            *(uint2*)(base + OFFK_BLO + s * LDB_KV + c8) = make_uint2(l01, l23);
        }
        __syncthreads();
        if (c + 1 < NC) {
            const int s_c = p * S_PER + (c + 1) * KC;
#pragma unroll
            for (int i = 0; i < 4; i++) {
                int idx = t + i * NT;
                int s = idx >> 4, c4 = (idx & 15) * 4;
                ra[i] = *(const float4*)(Vb + (size_t)(s_c + s) * DV_ + v0 + c4);
                rb[i] = *(const float4*)(Kb + (size_t)(s_c + s) * D_ + d0 + c4);
            }
        }
        warp_chunk_mma_kv(sb + (uint32_t)(c & 1) * BUF_KV, lane, wm, wn, acc);
    }

    // Epilogue: C[v,d] -> g_part
    float* dst = g_part + (size_t)(p * B_ + b) * DV_ * D_;
    const int rr = lane >> 2, cc = (lane & 3) * 2;
#pragma unroll
    for (int mi = 0; mi < 2; mi++)
#pragma unroll
        for (int ni = 0; ni < 4; ni++) {
            int row = v0 + wm + mi * 16 + rr;
            int col = d0 + wn + ni * 8 + cc;
            float* cp = acc[mi * 4 + ni];
            *(float2*)(dst + (size_t)row * D_ + col)       = make_float2(cp[0], cp[1]);
            *(float2*)(dst + (size_t)(row + 8) * D_ + col) = make_float2(cp[2], cp[3]);
        }
}

// ---------------------------------------------------------------------------
// Kernel 2: sum partials (fp32), split, write bf16 hi/lo KVT.
// ---------------------------------------------------------------------------
__global__ __launch_bounds__(256)
void reduce_kernel() {
    const int i = blockIdx.x * 256 + threadIdx.x;  // float4 group, 131072 total
    const size_t stride4 = (size_t)B_ * DV_ * D_ / 4;
    float4 acc = make_float4(0.f, 0.f, 0.f, 0.f);
#pragma unroll
    for (int p = 0; p < SPLITS; p++) {
        float4 v = ((const float4*)g_part)[p * stride4 + i];
        acc.x += v.x; acc.y += v.y; acc.z += v.z; acc.w += v.w;
    }
    uint32_t h01, l01, h23, l23;
    split2f(acc.x, acc.y, h01, l01);
    split2f(acc.z, acc.w, h23, l23);
    ((uint2*)g_KVThi)[i] = make_uint2(h01, h23);
    ((uint2*)g_KVTlo)[i] = make_uint2(l01, l23);
}

// ---------------------------------------------------------------------------
// Kernel 3: out[q,v] = (relu(Q)+eps)[q,d] @ KVT[v,d]^T
// 128-thread CTAs, tile 64(q) x 64(v). A from regs, B via cp.async.
// Grid (4, 64, B) = 2048 CTAs.
// ---------------------------------------------------------------------------
__global__ __launch_bounds__(NT, 4)
void out_kernel(const float* __restrict__ Q, float* __restrict__ O) {
    extern __shared__ __align__(16) char smem[];
    const uint32_t sb = smem_to_u32(smem);

    const int t = threadIdx.x, lane = t & 31, wid = t >> 5;
    const int wm = (wid & 1) * 32, wn = (wid >> 1) * 32;
    const int b = blockIdx.z;
    const int q0 = blockIdx.y * 64, v0 = blockIdx.x * 64;

    const float* __restrict__ Qb = Q + (size_t)b * S_ * D_;
    const __nv_bfloat16* __restrict__ Chi = g_KVThi + (size_t)b * DV_ * D_;
    const __nv_bfloat16* __restrict__ Clo = g_KVTlo + (size_t)b * DV_ * D_;

    float acc[8][4];
#pragma unroll
    for (int i = 0; i < 8; i++)
#pragma unroll
        for (int j = 0; j < 4; j++) acc[i][j] = 0.0f;

    // prologue: B(0) via cp.async, A(0) via LDG
    {
#pragma unroll
        for (int i = 0; i < 2; i++) {
            int idx = t + i * NT;
            int rowB = idx >> 2, sg = idx & 3;
            uint32_t doff = (uint32_t)(rowB * LDSB + sg * 16);
            cp_async16(sb + OFF_BHI + doff, Chi + (size_t)(v0 + rowB) * D_ + sg * 8);
            cp_async16(sb + OFF_BLO + doff, Clo + (size_t)(v0 + rowB) * D_ + sg * 8);
        }
        CP_COMMIT();
    }
    float4 rq[4];
#pragma unroll
    for (int i = 0; i < 4; i++) {
        int idx = t + i * NT;
        rq[i] = *(const float4*)(Qb + (size_t)(q0 + (idx >> 3)) * D_ + (idx & 7) * 4);
    }

    const int NC = D_ / KC;   // 8
    for (int c = 0; c < NC; c++) {
        char* base = smem + (size_t)(c & 1) * BUF_OUT;
#pragma unroll
        for (int i = 0; i < 4; i++) {
            int idx = t + i * NT;
            int row = idx >> 3, f4 = idx & 7;
            float a0 = fmaxf(rq[i].x, 0.f) + EPS_;
            float a1 = fmaxf(rq[i].y, 0.f) + EPS_;
            float a2 = fmaxf(rq[i].z, 0.f) + EPS_;
            float a3 = fmaxf(rq[i].w, 0.f) + EPS_;
            uint32_t h01, l01, h23, l23;
            split2f(a0, a1, h01, l01); split2f(a2, a3, h23, l23);
            *(uint2*)(base + OFF_AHI + row * LDSB + f4 * 8) = make_uint2(h01, h23);
            *(uint2*)(base + OFF_ALO + row * LDSB + f4 * 8) = make_uint2(l01, l23);
        }
        CP_WAIT0();          // B(c) landed (this thread's copies)
        __syncthreads();     // all copies + A staging visible
        if (c + 1 < NC) {
            const int dc = (c + 1) * KC;
            uint32_t nb = sb + (uint32_t)((~c & 1) * BUF_OUT);
#pragma unroll
            for (int i = 0; i < 2; i++) {
                int idx = t + i * NT;
                int rowB = idx >> 2, sg = idx & 3;
                uint32_t doff = (uint32_t)(rowB * LDSB + sg * 16);
                cp_async16(nb + OFF_BHI + doff, Chi + (size_t)(v0 + rowB) * D_ + dc + sg * 8);
                cp_async16(nb + OFF_BLO + doff, Clo + (size_t)(v0 + rowB) * D_ + dc + sg * 8);
            }
            CP_COMMIT();
#pragma unroll
            for (int i = 0; i < 4; i++) {
                int idx = t + i * NT;
                rq[i] = *(const float4*)(Qb + (size_t)(q0 + (idx >> 3)) * D_ + dc + (idx & 7) * 4);
            }
        }
        warp_chunk_mma_out(sb + (uint32_t)(c & 1) * BUF_OUT, lane, wm, wn, acc);
    }

    // Epilogue: C[q,v] -> O
    float* dst = O + (size_t)b * S_ * DV_;
    const int rr = lane >> 2, cc = (lane & 3) * 2;
#pragma unroll
    for (int mi = 0; mi < 2; mi++)
#pragma unroll
        for (int ni = 0; ni < 4; ni++) {
            int row = q0 + wm + mi * 16 + rr;
            int col = v0 + wn + ni * 8 + cc;
            float* cp = acc[mi * 4 + ni];
            *(float2*)(dst + (size_t)row * DV_ + col)       = make_float2(cp[0], cp[1]);
            *(float2*)(dst + (size_t)(row + 8) * DV_ + col) = make_float2(cp[2], cp[3]);
        }
}

extern "C" void kernel_launch(void* const* d_in, const int* in_sizes, int n_in,
                              void* d_out, int out_size) {
    const float* Q = (const float*)d_in[0];
    const float* K = (const float*)d_in[1];
    const float* V = (const float*)d_in[2];
    float* O = (float*)d_out;

    cudaFuncSetAttribute(kv_kernel,  cudaFuncAttributeMaxDynamicSharedMemorySize, SMEM_KV);
    cudaFuncSetAttribute(out_kernel, cudaFuncAttributeMaxDynamicSharedMemorySize, SMEM_OUT);

    kv_kernel<<<dim3(16, SPLITS, B_), NT, SMEM_KV>>>(K, V);
    reduce_kernel<<<512, 256>>>();
    out_kernel<<<dim3(4, 64, B_), NT, SMEM_OUT>>>(Q, O);
}

// round 13
// speedup vs baseline: 1.1146x; 1.0964x over previous
#include <cuda_runtime.h>
#include <cuda_bf16.h>
#include <cstdint>

#define B_  8
#define S_  4096
#define D_  256
#define DV_ 256
#define EPS_ 1e-6f

#define SPLITS 8
#define S_PER  (S_ / SPLITS)     // 512
#define KC     32                // k-chunk (bf16 elems)
#define NT     128               // threads per CTA (4 warps)

// ---------------- kv_kernel smem: [k][col] tiles, 64-wide (round-10) -------
#define LDA_KV 144               // 64 bf16 = 128B + 16 pad (4 words mod 32)
#define LDB_KV 144
#define A_TILE_KV (KC * LDA_KV)  // 4608
#define B_TILE_KV (KC * LDB_KV)  // 4608
#define OFFK_AHI 0
#define OFFK_ALO A_TILE_KV
#define OFFK_BHI (2 * A_TILE_KV)
#define OFFK_BLO (3 * A_TILE_KV)
#define BUF_KV   (4 * A_TILE_KV)                  // 18432
#define SMEM_KV  (2 * BUF_KV)                     // 36864

// ---------------- out_kernel smem: [row][k] tiles, A 64 rows / B 128 rows --
#define LDSB   80
#define TILEA64  (64 * LDSB)     // 5120
#define TILEB128 (128 * LDSB)    // 10240
#define OFF_AHI 0
#define OFF_ALO TILEA64
#define OFF_BHI (2 * TILEA64)
#define OFF_BLO (2 * TILEA64 + TILEB128)
#define BUF_OUT (2 * TILEA64 + 2 * TILEB128)      // 30720
#define SMEM_OUT (2 * BUF_OUT)                    // 61440

__device__ float g_part[SPLITS * B_ * DV_ * D_];   // 16 MB split-S partials
__device__ __nv_bfloat16 g_KVThi[B_ * DV_ * D_];   // KV^T hi [b][v][d]
__device__ __nv_bfloat16 g_KVTlo[B_ * DV_ * D_];   // KV^T lo [b][v][d]

// ---------------------------------------------------------------------------
__device__ __forceinline__ uint32_t smem_to_u32(const void* p) {
    uint32_t a;
    asm("{ .reg .u64 t; cvta.to.shared.u64 t, %1; cvt.u32.u64 %0, t; }"
        : "=r"(a) : "l"(p));
    return a;
}
__device__ __forceinline__ void ldmx4(uint32_t* r, uint32_t addr) {
    asm volatile("ldmatrix.sync.aligned.m8n8.x4.shared.b16 {%0,%1,%2,%3}, [%4];"
        : "=r"(r[0]), "=r"(r[1]), "=r"(r[2]), "=r"(r[3]) : "r"(addr));
}
__device__ __forceinline__ void ldmx4t(uint32_t* r, uint32_t addr) {
    asm volatile("ldmatrix.sync.aligned.m8n8.x4.trans.shared.b16 {%0,%1,%2,%3}, [%4];"
        : "=r"(r[0]), "=r"(r[1]), "=r"(r[2]), "=r"(r[3]) : "r"(addr));
}
__device__ __forceinline__ void mma16816(float* c, const uint32_t* a, const uint32_t* b) {
    asm volatile(
        "mma.sync.aligned.m16n8k16.row.col.f32.bf16.bf16.f32 "
        "{%0,%1,%2,%3}, {%4,%5,%6,%7}, {%8,%9}, {%0,%1,%2,%3};"
        : "+f"(c[0]), "+f"(c[1]), "+f"(c[2]), "+f"(c[3])
        : "r"(a[0]), "r"(a[1]), "r"(a[2]), "r"(a[3]), "r"(b[0]), "r"(b[1]));
}
__device__ __forceinline__ void cp_async16(uint32_t dst, const void* src) {
    asm volatile("cp.async.cg.shared.global [%0], [%1], 16;"
        :: "r"(dst), "l"(src) : "memory");
}
#define CP_COMMIT() asm volatile("cp.async.commit_group;" ::: "memory")
#define CP_WAIT0()  asm volatile("cp.async.wait_group 0;" ::: "memory")

// Truncation split: hi = top-16-bits (exact bf16), lo = rn_bf16(x - hi).
__device__ __forceinline__ void split2f(float x0, float x1, uint32_t& h, uint32_t& l) {
    uint32_t u0 = __float_as_uint(x0), u1 = __float_as_uint(x1);
    asm("prmt.b32 %0, %1, %2, 0x7632;" : "=r"(h) : "r"(u0), "r"(u1));
    float r0 = x0 - __uint_as_float(u0 & 0xFFFF0000u);
    float r1 = x1 - __uint_as_float(u1 & 0xFFFF0000u);
    asm("cvt.rn.bf16x2.f32 %0, %1, %2;" : "=r"(l) : "f"(r1), "f"(r0));
}

// ---------------------------------------------------------------------------
// kv MMA chunk: tiles [k][col] (64-wide), ldmatrix.trans. Warp tile 32x32.
// (round-10 proven)
// ---------------------------------------------------------------------------
__device__ __forceinline__ void warp_chunk_mma_kv(
    uint32_t buf, int lane, int wm, int wn, float (*acc)[4])
{
    const uint32_t aHi = buf + OFFK_AHI, aLo = buf + OFFK_ALO;
    const uint32_t bHi = buf + OFFK_BHI, bLo = buf + OFFK_BLO;
#pragma unroll
    for (int ks = 0; ks < 2; ks++) {
        int krA = ks * 16 + (lane & 7) + ((lane >> 4) & 1) * 8;
        int mcA = wm + ((lane >> 3) & 1) * 8;
        uint32_t aoff = (uint32_t)(krA * LDA_KV + mcA * 2);
        uint32_t ah[2][4], al[2][4];
#pragma unroll
        for (int mi = 0; mi < 2; mi++) {
            ldmx4t(ah[mi], aHi + aoff + mi * 32);
            ldmx4t(al[mi], aLo + aoff + mi * 32);
        }
        int krB = ks * 16 + (lane & 7) + ((lane >> 3) & 1) * 8;
        int ncB = wn + (lane >> 4) * 8;
        uint32_t boff = (uint32_t)(krB * LDB_KV + ncB * 2);
        uint32_t bh[4][2], bl[4][2];
#pragma unroll
        for (int pi = 0; pi < 2; pi++) {
            uint32_t r4[4];
            ldmx4t(r4, bHi + boff + pi * 32);
            bh[2*pi][0] = r4[0]; bh[2*pi][1] = r4[1];
            bh[2*pi+1][0] = r4[2]; bh[2*pi+1][1] = r4[3];
            ldmx4t(r4, bLo + boff + pi * 32);
            bl[2*pi][0] = r4[0]; bl[2*pi][1] = r4[1];
            bl[2*pi+1][0] = r4[2]; bl[2*pi+1][1] = r4[3];
        }
#pragma unroll
        for (int mi = 0; mi < 2; mi++)
#pragma unroll
            for (int ni = 0; ni < 4; ni++)
                mma16816(acc[mi * 4 + ni], ah[mi], bh[ni]);
#pragma unroll
        for (int mi = 0; mi < 2; mi++)
#pragma unroll
            for (int ni = 0; ni < 4; ni++)
                mma16816(acc[mi * 4 + ni], ah[mi], bl[ni]);
#pragma unroll
        for (int mi = 0; mi < 2; mi++)
#pragma unroll
            for (int ni = 0; ni < 4; ni++)
                mma16816(acc[mi * 4 + ni], al[mi], bh[ni]);
    }
}

// out MMA chunk: A 64 rows [row][k], B 128 rows [row][k]. Warp tile 32x64.
// acc[mi*8+ni][4], mi<2, ni<8. (round-7 fragment path, 8 n-frags)
__device__ __forceinline__ void warp_chunk_mma_out(
    uint32_t buf, int lane, int wm, int wn, float (*acc)[4])
{
    const uint32_t aHi = buf + OFF_AHI, aLo = buf + OFF_ALO;
    const uint32_t bHi = buf + OFF_BHI, bLo = buf + OFF_BLO;
#pragma unroll
    for (int ks = 0; ks < 2; ks++) {
        uint32_t aoff = (uint32_t)((wm + (lane & 15)) * LDSB
                                   + ((lane >> 4) * 8 + ks * 16) * 2);
        uint32_t ah[2][4], al[2][4];
#pragma unroll
        for (int mi = 0; mi < 2; mi++) {
            ldmx4(ah[mi], aHi + aoff + mi * 16 * LDSB);
            ldmx4(al[mi], aLo + aoff + mi * 16 * LDSB);
        }
        uint32_t boff = (uint32_t)((wn + (lane & 7) + ((lane >> 4) << 3)) * LDSB
                                   + (((lane >> 3) & 1) * 8 + ks * 16) * 2);
        uint32_t bh[8][2], bl[8][2];
#pragma unroll
        for (int pi = 0; pi < 4; pi++) {
            uint32_t r4[4];
            ldmx4(r4, bHi + boff + pi * 16 * LDSB);
            bh[2*pi][0] = r4[0]; bh[2*pi][1] = r4[1];
            bh[2*pi+1][0] = r4[2]; bh[2*pi+1][1] = r4[3];
            ldmx4(r4, bLo + boff + pi * 16 * LDSB);
            bl[2*pi][0] = r4[0]; bl[2*pi][1] = r4[1];
            bl[2*pi+1][0] = r4[2]; bl[2*pi+1][1] = r4[3];
        }
#pragma unroll
        for (int mi = 0; mi < 2; mi++)
#pragma unroll
            for (int ni = 0; ni < 8; ni++)
                mma16816(acc[mi * 8 + ni], ah[mi], bh[ni]);
#pragma unroll
        for (int mi = 0; mi < 2; mi++)
#pragma unroll
            for (int ni = 0; ni < 8; ni++)
                mma16816(acc[mi * 8 + ni], ah[mi], bl[ni]);
#pragma unroll
        for (int mi = 0; mi < 2; mi++)
#pragma unroll
            for (int ni = 0; ni < 8; ni++)
                mma16816(acc[mi * 8 + ni], al[mi], bh[ni]);
    }
}

// ---------------------------------------------------------------------------
// Kernel 1: partial KV^T[v,d] = sum_{s in split} V[s,v] * (relu(K[s,d])+eps)
// EXACT round-10 config: 128-thr CTAs, 64x64 tiles, occ 4.
// Grid (16, SPLITS=8, B) = 1024 CTAs.
// ---------------------------------------------------------------------------
__global__ __launch_bounds__(NT, 4)
void kv_kernel(const float* __restrict__ K, const float* __restrict__ V) {
    extern __shared__ __align__(16) char smem[];
    const uint32_t sb = smem_to_u32(smem);

    const int t = threadIdx.x, lane = t & 31, wid = t >> 5;
    const int wm = (wid & 1) * 32, wn = (wid >> 1) * 32;
    const int b = blockIdx.z, p = blockIdx.y;
    const int v0 = (blockIdx.x & 3) * 64, d0 = (blockIdx.x >> 2) * 64;

    const float* __restrict__ Vb = V + (size_t)b * S_ * DV_;
    const float* __restrict__ Kb = K + (size_t)b * S_ * D_;

    float acc[8][4];
#pragma unroll
    for (int i = 0; i < 8; i++)
#pragma unroll
        for (int j = 0; j < 4; j++) acc[i][j] = 0.0f;

    // slots: idx = t + i*128 (i<4): s = idx>>4 (0..31), c4 = (idx&15)*4
    float4 ra[4], rb[4];
    {
        const int s_c = p * S_PER;
#pragma unroll
        for (int i = 0; i < 4; i++) {
            int idx = t + i * NT;
            int s = idx >> 4, c4 = (idx & 15) * 4;
            ra[i] = *(const float4*)(Vb + (size_t)(s_c + s) * DV_ + v0 + c4);
            rb[i] = *(const float4*)(Kb + (size_t)(s_c + s) * D_ + d0 + c4);
        }
    }

    const int NC = S_PER / KC;   // 16
    for (int c = 0; c < NC; c++) {
        char* base = smem + (size_t)(c & 1) * BUF_KV;
#pragma unroll
        for (int i = 0; i < 4; i++) {
            int idx = t + i * NT;
            int s = idx >> 4, c8 = (idx & 15) * 8;
            uint32_t h01, l01, h23, l23;
            split2f(ra[i].x, ra[i].y, h01, l01);
            split2f(ra[i].z, ra[i].w, h23, l23);
            *(uint2*)(base + OFFK_AHI + s * LDA_KV + c8) = make_uint2(h01, h23);
            *(uint2*)(base + OFFK_ALO + s * LDA_KV + c8) = make_uint2(l01, l23);
            float b0 = fmaxf(rb[i].x, 0.f) + EPS_;
            float b1 = fmaxf(rb[i].y, 0.f) + EPS_;
            float b2 = fmaxf(rb[i].z, 0.f) + EPS_;
            float b3 = fmaxf(rb[i].w, 0.f) + EPS_;
            split2f(b0, b1, h01, l01);
            split2f(b2, b3, h23, l23);
            *(uint2*)(base + OFFK_BHI + s * LDB_KV + c8) = make_uint2(h01, h23);
            *(uint2*)(base + OFFK_BLO + s * LDB_KV + c8) = make_uint2(l01, l23);
        }
        __syncthreads();
        if (c + 1 < NC) {
            const int s_c = p * S_PER + (c + 1) * KC;
#pragma unroll
            for (int i = 0; i < 4; i++) {
                int idx = t + i * NT;
                int s = idx >> 4, c4 = (idx & 15) * 4;
                ra[i] = *(const float4*)(Vb + (size_t)(s_c + s) * DV_ + v0 + c4);
                rb[i] = *(const float4*)(Kb + (size_t)(s_c + s) * D_ + d0 + c4);
            }
        }
        warp_chunk_mma_kv(sb + (uint32_t)(c & 1) * BUF_KV, lane, wm, wn, acc);
    }

    // Epilogue: C[v,d] -> g_part
    float* dst = g_part + (size_t)(p * B_ + b) * DV_ * D_;
    const int rr = lane >> 2, cc = (lane & 3) * 2;
#pragma unroll
    for (int mi = 0; mi < 2; mi++)
#pragma unroll
        for (int ni = 0; ni < 4; ni++) {
            int row = v0 + wm + mi * 16 + rr;
            int col = d0 + wn + ni * 8 + cc;
            float* cp = acc[mi * 4 + ni];
            *(float2*)(dst + (size_t)row * D_ + col)       = make_float2(cp[0], cp[1]);
            *(float2*)(dst + (size_t)(row + 8) * D_ + col) = make_float2(cp[2], cp[3]);
        }
}

// ---------------------------------------------------------------------------
// Kernel 2: sum partials (fp32), split, write bf16 hi/lo KVT.
// ---------------------------------------------------------------------------
__global__ __launch_bounds__(256)
void reduce_kernel() {
    const int i = blockIdx.x * 256 + threadIdx.x;  // float4 group, 131072 total
    const size_t stride4 = (size_t)B_ * DV_ * D_ / 4;
    float4 acc = make_float4(0.f, 0.f, 0.f, 0.f);
#pragma unroll
    for (int p = 0; p < SPLITS; p++) {
        float4 v = ((const float4*)g_part)[p * stride4 + i];
        acc.x += v.x; acc.y += v.y; acc.z += v.z; acc.w += v.w;
    }
    uint32_t h01, l01, h23, l23;
    split2f(acc.x, acc.y, h01, l01);
    split2f(acc.z, acc.w, h23, l23);
    ((uint2*)g_KVThi)[i] = make_uint2(h01, h23);
    ((uint2*)g_KVTlo)[i] = make_uint2(l01, l23);
}

// ---------------------------------------------------------------------------
// Kernel 3: out[q,v] = (relu(Q)+eps)[q,d] @ KVT[v,d]^T
// NEW: tile 64(q) x 128(v), warp tile 32x64, occ 3. A from regs, B cp.async.
// Grid (2, 64, B) = 1024 CTAs.
// ---------------------------------------------------------------------------
__global__ __launch_bounds__(NT, 3)
void out_kernel(const float* __restrict__ Q, float* __restrict__ O) {
    extern __shared__ __align__(16) char smem[];
    const uint32_t sb = smem_to_u32(smem);

    const int t = threadIdx.x, lane = t & 31, wid = t >> 5;
    const int wm = (wid & 1) * 32, wn = (wid >> 1) * 64;
    const int b = blockIdx.z;
    const int q0 = blockIdx.y * 64, v0 = blockIdx.x * 128;

    const float* __restrict__ Qb = Q + (size_t)b * S_ * D_;
    const __nv_bfloat16* __restrict__ Chi = g_KVThi + (size_t)b * DV_ * D_;
    const __nv_bfloat16* __restrict__ Clo = g_KVTlo + (size_t)b * DV_ * D_;

    float acc[16][4];
#pragma unroll
    for (int i = 0; i < 16; i++)
#pragma unroll
        for (int j = 0; j < 4; j++) acc[i][j] = 0.0f;

    // prologue: B(0) via cp.async (128 rows: 4 slots), A(0) via LDG (4 slots)
    {
#pragma unroll
        for (int i = 0; i < 4; i++) {
            int idx = t + i * NT;
            int rowB = idx >> 2, sg = idx & 3;
            uint32_t doff = (uint32_t)(rowB * LDSB + sg * 16);
            cp_async16(sb + OFF_BHI + doff, Chi + (size_t)(v0 + rowB) * D_ + sg * 8);
            cp_async16(sb + OFF_BLO + doff, Clo + (size_t)(v0 + rowB) * D_ + sg * 8);
        }
        CP_COMMIT();
    }
    float4 rq[4];
#pragma unroll
    for (int i = 0; i < 4; i++) {
        int idx = t + i * NT;
        rq[i] = *(const float4*)(Qb + (size_t)(q0 + (idx >> 3)) * D_ + (idx & 7) * 4);
    }

    const int NC = D_ / KC;   // 8
    for (int c = 0; c < NC; c++) {
        char* base = smem + (size_t)(c & 1) * BUF_OUT;
#pragma unroll
        for (int i = 0; i < 4; i++) {
            int idx = t + i * NT;
            int row = idx >> 3, f4 = idx & 7;
            float a0 = fmaxf(rq[i].x, 0.f) + EPS_;
            float a1 = fmaxf(rq[i].y, 0.f) + EPS_;
            float a2 = fmaxf(rq[i].z, 0.f) + EPS_;
            float a3 = fmaxf(rq[i].w, 0.f) + EPS_;
            uint32_t h01, l01, h23, l23;
            split2f(a0, a1, h01, l01); split2f(a2, a3, h23, l23);
            *(uint2*)(base + OFF_AHI + row * LDSB + f4 * 8) = make_uint2(h01, h23);
            *(uint2*)(base + OFF_ALO + row * LDSB + f4 * 8) = make_uint2(l01, l23);
        }
        CP_WAIT0();          // B(c) landed (this thread's copies)
        __syncthreads();     // all copies + A staging visible
        if (c + 1 < NC) {
            const int dc = (c + 1) * KC;
            uint32_t nb = sb + (uint32_t)((~c & 1) * BUF_OUT);
#pragma unroll
            for (int i = 0; i < 4; i++) {
                int idx = t + i * NT;
                int rowB = idx >> 2, sg = idx & 3;
                uint32_t doff = (uint32_t)(rowB * LDSB + sg * 16);
                cp_async16(nb + OFF_BHI + doff, Chi + (size_t)(v0 + rowB) * D_ + dc + sg * 8);
                cp_async16(nb + OFF_BLO + doff, Clo + (size_t)(v0 + rowB) * D_ + dc + sg * 8);
            }
            CP_COMMIT();
#pragma unroll
            for (int i = 0; i < 4; i++) {
                int idx = t + i * NT;
                rq[i] = *(const float4*)(Qb + (size_t)(q0 + (idx >> 3)) * D_ + dc + (idx & 7) * 4);
            }
        }
        warp_chunk_mma_out(sb + (uint32_t)(c & 1) * BUF_OUT, lane, wm, wn, acc);
    }

    // Epilogue: C[q,v] -> O
    float* dst = O + (size_t)b * S_ * DV_;
    const int rr = lane >> 2, cc = (lane & 3) * 2;
#pragma unroll
    for (int mi = 0; mi < 2; mi++)
#pragma unroll
        for (int ni = 0; ni < 8; ni++) {
            int row = q0 + wm + mi * 16 + rr;
            int col = v0 + wn + ni * 8 + cc;
            float* cp = acc[mi * 8 + ni];
            *(float2*)(dst + (size_t)row * DV_ + col)       = make_float2(cp[0], cp[1]);
            *(float2*)(dst + (size_t)(row + 8) * DV_ + col) = make_float2(cp[2], cp[3]);
        }
}

extern "C" void kernel_launch(void* const* d_in, const int* in_sizes, int n_in,
                              void* d_out, int out_size) {
    const float* Q = (const float*)d_in[0];
    const float* K = (const float*)d_in[1];
    const float* V = (const float*)d_in[2];
    float* O = (float*)d_out;

    cudaFuncSetAttribute(kv_kernel,  cudaFuncAttributeMaxDynamicSharedMemorySize, SMEM_KV);
    cudaFuncSetAttribute(out_kernel, cudaFuncAttributeMaxDynamicSharedMemorySize, SMEM_OUT);

    kv_kernel<<<dim3(16, SPLITS, B_), NT, SMEM_KV>>>(K, V);
    reduce_kernel<<<512, 256>>>();
    out_kernel<<<dim3(2, 64, B_), NT, SMEM_OUT>>>(Q, O);
}

// round 14
// speedup vs baseline: 1.5316x; 1.3742x over previous
#include <cuda_runtime.h>
#include <cuda_fp16.h>
#include <cstdint>

#define B_  8
#define S_  4096
#define D_  256
#define DV_ 256
#define EPS_ 1e-6f

#define SPLITS 8
#define S_PER  (S_ / SPLITS)     // 512
#define KC     32                // k-chunk (fp16 elems)
#define NT     128               // threads per CTA (4 warps)

// ---------------- kv_kernel smem: [k][col] fp16 tiles, 64-wide -------------
#define LDA_KV 144               // 64 fp16 = 128B + 16 pad
#define LDB_KV 144
#define A_TILE_KV (KC * LDA_KV)  // 4608
#define OFFK_A 0
#define OFFK_B A_TILE_KV
#define BUF_KV (2 * A_TILE_KV)   // 9216
#define SMEM_KV (2 * BUF_KV)     // 18432

// ---------------- out_kernel smem: [row][k] fp16 tiles ----------------------
#define LDSB   80                // 32 fp16 = 64B + 16 pad
#define TILEA64  (64 * LDSB)     // 5120
#define TILEB128 (128 * LDSB)    // 10240
#define OFF_A 0
#define OFF_B TILEA64
#define BUF_OUT (TILEA64 + TILEB128)   // 15360
#define SMEM_OUT (2 * BUF_OUT)         // 30720

__device__ float g_part[SPLITS * B_ * DV_ * D_];   // 16 MB fp32 split-S partials
__device__ __half g_KVTh[B_ * DV_ * D_];           // KV^T fp16 [b][v][d]

// ---------------------------------------------------------------------------
__device__ __forceinline__ uint32_t smem_to_u32(const void* p) {
    uint32_t a;
    asm("{ .reg .u64 t; cvta.to.shared.u64 t, %1; cvt.u32.u64 %0, t; }"
        : "=r"(a) : "l"(p));
    return a;
}
__device__ __forceinline__ void ldmx4(uint32_t* r, uint32_t addr) {
    asm volatile("ldmatrix.sync.aligned.m8n8.x4.shared.b16 {%0,%1,%2,%3}, [%4];"
        : "=r"(r[0]), "=r"(r[1]), "=r"(r[2]), "=r"(r[3]) : "r"(addr));
}
__device__ __forceinline__ void ldmx4t(uint32_t* r, uint32_t addr) {
    asm volatile("ldmatrix.sync.aligned.m8n8.x4.trans.shared.b16 {%0,%1,%2,%3}, [%4];"
        : "=r"(r[0]), "=r"(r[1]), "=r"(r[2]), "=r"(r[3]) : "r"(addr));
}
__device__ __forceinline__ void mma16816h(float* c, const uint32_t* a, const uint32_t* b) {
    asm volatile(
        "mma.sync.aligned.m16n8k16.row.col.f32.f16.f16.f32 "
        "{%0,%1,%2,%3}, {%4,%5,%6,%7}, {%8,%9}, {%0,%1,%2,%3};"
        : "+f"(c[0]), "+f"(c[1]), "+f"(c[2]), "+f"(c[3])
        : "r"(a[0]), "r"(a[1]), "r"(a[2]), "r"(a[3]), "r"(b[0]), "r"(b[1]));
}
__device__ __forceinline__ void cp_async16(uint32_t dst, const void* src) {
    asm volatile("cp.async.cg.shared.global [%0], [%1], 16;"
        :: "r"(dst), "l"(src) : "memory");
}
#define CP_COMMIT() asm volatile("cp.async.commit_group;" ::: "memory")
#define CP_WAIT0()  asm volatile("cp.async.wait_group 0;" ::: "memory")

// pack 2 floats -> fp16x2 (memory order x0,x1; first asm src = high half,
// same convention as the verified bf16 path)
__device__ __forceinline__ uint32_t cvt2h(float x0, float x1) {
    uint32_t r;
    asm("cvt.rn.f16x2.f32 %0, %1, %2;" : "=r"(r) : "f"(x1), "f"(x0));
    return r;
}

// ---------------------------------------------------------------------------
// kv MMA chunk: fp16 tiles [k][col] (64-wide), ldmatrix.trans. Warp 32x32.
// ---------------------------------------------------------------------------
__device__ __forceinline__ void warp_chunk_mma_kv(
    uint32_t buf, int lane, int wm, int wn, float (*acc)[4])
{
    const uint32_t aT = buf + OFFK_A, bT = buf + OFFK_B;
#pragma unroll
    for (int ks = 0; ks < 2; ks++) {
        int krA = ks * 16 + (lane & 7) + ((lane >> 4) & 1) * 8;
        int mcA = wm + ((lane >> 3) & 1) * 8;
        uint32_t aoff = (uint32_t)(krA * LDA_KV + mcA * 2);
        uint32_t ah[2][4];
#pragma unroll
        for (int mi = 0; mi < 2; mi++)
            ldmx4t(ah[mi], aT + aoff + mi * 32);

        int krB = ks * 16 + (lane & 7) + ((lane >> 3) & 1) * 8;
        int ncB = wn + (lane >> 4) * 8;
        uint32_t boff = (uint32_t)(krB * LDB_KV + ncB * 2);
        uint32_t bh[4][2];
#pragma unroll
        for (int pi = 0; pi < 2; pi++) {
            uint32_t r4[4];
            ldmx4t(r4, bT + boff + pi * 32);
            bh[2*pi][0] = r4[0]; bh[2*pi][1] = r4[1];
            bh[2*pi+1][0] = r4[2]; bh[2*pi+1][1] = r4[3];
        }
#pragma unroll
        for (int mi = 0; mi < 2; mi++)
#pragma unroll
            for (int ni = 0; ni < 4; ni++)
                mma16816h(acc[mi * 4 + ni], ah[mi], bh[ni]);
    }
}

// out MMA chunk: fp16 tiles [row][k], warp tile 32x64 (8 n-frags).
__device__ __forceinline__ void warp_chunk_mma_out(
    uint32_t buf, int lane, int wm, int wn, float (*acc)[4])
{
    const uint32_t aT = buf + OFF_A, bT = buf + OFF_B;
#pragma unroll
    for (int ks = 0; ks < 2; ks++) {
        uint32_t aoff = (uint32_t)((wm + (lane & 15)) * LDSB
                                   + ((lane >> 4) * 8 + ks * 16) * 2);
        uint32_t ah[2][4];
#pragma unroll
        for (int mi = 0; mi < 2; mi++)
            ldmx4(ah[mi], aT + aoff + mi * 16 * LDSB);

        uint32_t boff = (uint32_t)((wn + (lane & 7) + ((lane >> 4) << 3)) * LDSB
                                   + (((lane >> 3) & 1) * 8 + ks * 16) * 2);
        uint32_t bh[8][2];
#pragma unroll
        for (int pi = 0; pi < 4; pi++) {
            uint32_t r4[4];
            ldmx4(r4, bT + boff + pi * 16 * LDSB);
            bh[2*pi][0] = r4[0]; bh[2*pi][1] = r4[1];
            bh[2*pi+1][0] = r4[2]; bh[2*pi+1][1] = r4[3];
        }
#pragma unroll
        for (int mi = 0; mi < 2; mi++)
#pragma unroll
            for (int ni = 0; ni < 8; ni++)
                mma16816h(acc[mi * 8 + ni], ah[mi], bh[ni]);
    }
}

// ---------------------------------------------------------------------------
// Kernel 1: partial KV^T[v,d] = sum_{s in split} V[s,v] * (relu(K[s,d])+eps)
// fp16 single-product. Grid (16, SPLITS=8, B) = 1024 CTAs, occ 4.
// ---------------------------------------------------------------------------
__global__ __launch_bounds__(NT, 4)
void kv_kernel(const float* __restrict__ K, const float* __restrict__ V) {
    extern __shared__ __align__(16) char smem[];
    const uint32_t sb = smem_to_u32(smem);

    const int t = threadIdx.x, lane = t & 31, wid = t >> 5;
    const int wm = (wid & 1) * 32, wn = (wid >> 1) * 32;
    const int b = blockIdx.z, p = blockIdx.y;
    const int v0 = (blockIdx.x & 3) * 64, d0 = (blockIdx.x >> 2) * 64;

    const float* __restrict__ Vb = V + (size_t)b * S_ * DV_;
    const float* __restrict__ Kb = K + (size_t)b * S_ * D_;

    float acc[8][4];
#pragma unroll
    for (int i = 0; i < 8; i++)
#pragma unroll
        for (int j = 0; j < 4; j++) acc[i][j] = 0.0f;

    // slots: idx = t + i*128 (i<4): s = idx>>4 (0..31), c4 = (idx&15)*4
    float4 ra[4], rb[4];
    {
        const int s_c = p * S_PER;
#pragma unroll
        for (int i = 0; i < 4; i++) {
            int idx = t + i * NT;
            int s = idx >> 4, c4 = (idx & 15) * 4;
            ra[i] = *(const float4*)(Vb + (size_t)(s_c + s) * DV_ + v0 + c4);
            rb[i] = *(const float4*)(Kb + (size_t)(s_c + s) * D_ + d0 + c4);
        }
    }

    const int NC = S_PER / KC;   // 16
    for (int c = 0; c < NC; c++) {
        char* base = smem + (size_t)(c & 1) * BUF_KV;
#pragma unroll
        for (int i = 0; i < 4; i++) {
            int idx = t + i * NT;
            int s = idx >> 4, c8 = (idx & 15) * 8;
            // A = V (no transform)
            *(uint2*)(base + OFFK_A + s * LDA_KV + c8) =
                make_uint2(cvt2h(ra[i].x, ra[i].y), cvt2h(ra[i].z, ra[i].w));
            // B = relu(K)+eps
            float b0 = fmaxf(rb[i].x, 0.f) + EPS_;
            float b1 = fmaxf(rb[i].y, 0.f) + EPS_;
            float b2 = fmaxf(rb[i].z, 0.f) + EPS_;
            float b3 = fmaxf(rb[i].w, 0.f) + EPS_;
            *(uint2*)(base + OFFK_B + s * LDB_KV + c8) =
                make_uint2(cvt2h(b0, b1), cvt2h(b2, b3));
        }
        __syncthreads();
        if (c + 1 < NC) {
            const int s_c = p * S_PER + (c + 1) * KC;
#pragma unroll
            for (int i = 0; i < 4; i++) {
                int idx = t + i * NT;
                int s = idx >> 4, c4 = (idx & 15) * 4;
                ra[i] = *(const float4*)(Vb + (size_t)(s_c + s) * DV_ + v0 + c4);
                rb[i] = *(const float4*)(Kb + (size_t)(s_c + s) * D_ + d0 + c4);
            }
        }
        warp_chunk_mma_kv(sb + (uint32_t)(c & 1) * BUF_KV, lane, wm, wn, acc);
    }

    // Epilogue: C[v,d] -> g_part (fp32)
    float* dst = g_part + (size_t)(p * B_ + b) * DV_ * D_;
    const int rr = lane >> 2, cc = (lane & 3) * 2;
#pragma unroll
    for (int mi = 0; mi < 2; mi++)
#pragma unroll
        for (int ni = 0; ni < 4; ni++) {
            int row = v0 + wm + mi * 16 + rr;
            int col = d0 + wn + ni * 8 + cc;
            float* cp = acc[mi * 4 + ni];
            *(float2*)(dst + (size_t)row * D_ + col)       = make_float2(cp[0], cp[1]);
            *(float2*)(dst + (size_t)(row + 8) * D_ + col) = make_float2(cp[2], cp[3]);
        }
}

// ---------------------------------------------------------------------------
// Kernel 2: sum partials (fp32), single rn to fp16 KVT.
// ---------------------------------------------------------------------------
__global__ __launch_bounds__(256)
void reduce_kernel() {
    const int i = blockIdx.x * 256 + threadIdx.x;  // float4 group, 131072 total
    const size_t stride4 = (size_t)B_ * DV_ * D_ / 4;
    float4 acc = make_float4(0.f, 0.f, 0.f, 0.f);
#pragma unroll
    for (int p = 0; p < SPLITS; p++) {
        float4 v = ((const float4*)g_part)[p * stride4 + i];
        acc.x += v.x; acc.y += v.y; acc.z += v.z; acc.w += v.w;
    }
    ((uint2*)g_KVTh)[i] = make_uint2(cvt2h(acc.x, acc.y), cvt2h(acc.z, acc.w));
}

// ---------------------------------------------------------------------------
// Kernel 3: out[q,v] = (relu(Q)+eps)[q,d] @ KVT[v,d]^T
// Tile 64(q) x 128(v), warp 32x64, occ 4. A relu+cvt from regs, B cp.async fp16.
// Grid (2, 64, B) = 1024 CTAs.
// ---------------------------------------------------------------------------
__global__ __launch_bounds__(NT, 4)
void out_kernel(const float* __restrict__ Q, float* __restrict__ O) {
    extern __shared__ __align__(16) char smem[];
    const uint32_t sb = smem_to_u32(smem);

    const int t = threadIdx.x, lane = t & 31, wid = t >> 5;
    const int wm = (wid & 1) * 32, wn = (wid >> 1) * 64;
    const int b = blockIdx.z;
    const int q0 = blockIdx.y * 64, v0 = blockIdx.x * 128;

    const float* __restrict__ Qb = Q + (size_t)b * S_ * D_;
    const __half* __restrict__ Ch = g_KVTh + (size_t)b * DV_ * D_;

    float acc[16][4];
#pragma unroll
    for (int i = 0; i < 16; i++)
#pragma unroll
        for (int j = 0; j < 4; j++) acc[i][j] = 0.0f;

    // B cp.async (i<4): idx = t + i*128; rowB = idx>>2 (0..127), sg = idx&3 (16B)
    // prologue: B(0) via cp.async, A(0) via LDG
    {
#pragma unroll
        for (int i = 0; i < 4; i++) {
            int idx = t + i * NT;
            int rowB = idx >> 2, sg = idx & 3;
            cp_async16(sb + OFF_B + (uint32_t)(rowB * LDSB + sg * 16),
                       Ch + (size_t)(v0 + rowB) * D_ + sg * 8);
        }
        CP_COMMIT();
    }
    float4 rq[4];
#pragma unroll
    for (int i = 0; i < 4; i++) {
        int idx = t + i * NT;
        rq[i] = *(const float4*)(Qb + (size_t)(q0 + (idx >> 3)) * D_ + (idx & 7) * 4);
    }

    const int NC = D_ / KC;   // 8
    for (int c = 0; c < NC; c++) {
        char* base = smem + (size_t)(c & 1) * BUF_OUT;
#pragma unroll
        for (int i = 0; i < 4; i++) {
            int idx = t + i * NT;
            int row = idx >> 3, f4 = idx & 7;
            float a0 = fmaxf(rq[i].x, 0.f) + EPS_;
            float a1 = fmaxf(rq[i].y, 0.f) + EPS_;
            float a2 = fmaxf(rq[i].z, 0.f) + EPS_;
            float a3 = fmaxf(rq[i].w, 0.f) + EPS_;
            *(uint2*)(base + OFF_A + row * LDSB + f4 * 8) =
                make_uint2(cvt2h(a0, a1), cvt2h(a2, a3));
        }
        CP_WAIT0();          // B(c) landed (this thread's copies)
        __syncthreads();     // all copies + A staging visible
        if (c + 1 < NC) {
            const int dc = (c + 1) * KC;
            uint32_t nb = sb + (uint32_t)((~c & 1) * BUF_OUT);
#pragma unroll
            for (int i = 0; i < 4; i++) {
                int idx = t + i * NT;
                int rowB = idx >> 2, sg = idx & 3;
                cp_async16(nb + OFF_B + (uint32_t)(rowB * LDSB + sg * 16),
                           Ch + (size_t)(v0 + rowB) * D_ + dc + sg * 8);
            }
            CP_COMMIT();
#pragma unroll
            for (int i = 0; i < 4; i++) {
                int idx = t + i * NT;
                rq[i] = *(const float4*)(Qb + (size_t)(q0 + (idx >> 3)) * D_ + dc + (idx & 7) * 4);
            }
        }
        warp_chunk_mma_out(sb + (uint32_t)(c & 1) * BUF_OUT, lane, wm, wn, acc);
    }

    // Epilogue: C[q,v] -> O
    float* dst = O + (size_t)b * S_ * DV_;
    const int rr = lane >> 2, cc = (lane & 3) * 2;
#pragma unroll
    for (int mi = 0; mi < 2; mi++)
#pragma unroll
        for (int ni = 0; ni < 8; ni++) {
            int row = q0 + wm + mi * 16 + rr;
            int col = v0 + wn + ni * 8 + cc;
            float* cp = acc[mi * 8 + ni];
            *(float2*)(dst + (size_t)row * DV_ + col)       = make_float2(cp[0], cp[1]);
            *(float2*)(dst + (size_t)(row + 8) * DV_ + col) = make_float2(cp[2], cp[3]);
        }
}

extern "C" void kernel_launch(void* const* d_in, const int* in_sizes, int n_in,
                              void* d_out, int out_size) {
    const float* Q = (const float*)d_in[0];
    const float* K = (const float*)d_in[1];
    const float* V = (const float*)d_in[2];
    float* O = (float*)d_out;

    cudaFuncSetAttribute(kv_kernel,  cudaFuncAttributeMaxDynamicSharedMemorySize, SMEM_KV);
    cudaFuncSetAttribute(out_kernel, cudaFuncAttributeMaxDynamicSharedMemorySize, SMEM_OUT);

    kv_kernel<<<dim3(16, SPLITS, B_), NT, SMEM_KV>>>(K, V);
    reduce_kernel<<<512, 256>>>();
    out_kernel<<<dim3(2, 64, B_), NT, SMEM_OUT>>>(Q, O);
}